// round 15
// baseline (speedup 1.0000x reference)
#include <cuda_runtime.h>
#include <math.h>

#define BB   16
#define SS   1024
#define EE   256
#define HH   256
#define G4   1024
#define WT_  256

// ---------- static scratch ----------
__device__ float g_Af[(size_t)BB * SS * G4];
__device__ float g_Ab[(size_t)BB * SS * G4];
__device__ float g_G [(size_t)BB * SS * G4];
__device__ float g_hn[(size_t)BB * SS * HH];
__device__ float g_hb[(size_t)BB * SS * HH];
__device__ float g_P [(size_t)BB * SS * WT_];
__device__ float g_b3[(size_t)BB * SS * WT_];
__device__ float g_WTf[G4 * HH];
__device__ float g_WTb[G4 * HH];
__device__ float g_WTd[G4 * HH];
__device__ int   g_flagG[128];      // (tchunk*16 + b) -> completed x-tiles (8 = done)

// ---------- helpers ----------
__device__ __forceinline__ unsigned long long fma2(unsigned long long a,
                                                   unsigned long long b,
                                                   unsigned long long c) {
    unsigned long long d;
    asm("fma.rn.f32x2 %0, %1, %2, %3;" : "=l"(d) : "l"(a), "l"(b), "l"(c));
    return d;
}
__device__ __forceinline__ unsigned long long splat2(float a) {
    unsigned long long d; unsigned int u = __float_as_uint(a);
    asm("mov.b64 %0, {%1, %1};" : "=l"(d) : "r"(u));
    return d;
}
__device__ __forceinline__ float2 unpk(unsigned long long v) {
    float2 r;
    asm("mov.b64 {%0, %1}, %2;" : "=f"(r.x), "=f"(r.y) : "l"(v));
    return r;
}
__device__ __forceinline__ float sigf(float x) { return 1.0f / (1.0f + expf(-x)); }

__device__ __forceinline__ unsigned int smem_u32(const void* p) {
    unsigned int a;
    asm("{ .reg .u64 t; cvta.to.shared.u64 t, %1; cvt.u32.u64 %0, t; }" : "=r"(a) : "l"(p));
    return a;
}
__device__ __forceinline__ void st_cluster_f32(unsigned int addr, unsigned int rank, float v) {
    unsigned int ra;
    asm volatile("mapa.shared::cluster.u32 %0, %1, %2;" : "=r"(ra) : "r"(addr), "r"(rank));
    asm volatile("st.shared::cluster.f32 [%0], %1;" :: "r"(ra), "f"(v) : "memory");
}
__device__ __forceinline__ void cluster_sync() {
    asm volatile("barrier.cluster.arrive.aligned;" ::: "memory");
    asm volatile("barrier.cluster.wait.aligned;"   ::: "memory");
}
__device__ __forceinline__ int ld_acq(const int* p) {
    int v;
    asm volatile("ld.acquire.gpu.global.b32 %0, [%1];" : "=r"(v) : "l"(p) : "memory");
    return v;
}

// ---------- fused transpose: 3x [256,1024] -> [1024,256] ----------
__global__ void transpose_w3(const float* __restrict__ i0, const float* __restrict__ i1,
                             const float* __restrict__ i2,
                             float* __restrict__ o0, float* __restrict__ o1,
                             float* __restrict__ o2) {
    const float* in  = blockIdx.z == 0 ? i0 : (blockIdx.z == 1 ? i1 : i2);
    float*       out = blockIdx.z == 0 ? o0 : (blockIdx.z == 1 ? o1 : o2);
    __shared__ float tile[32][33];
    int x = blockIdx.x * 32 + threadIdx.x;
    int y = blockIdx.y * 32 + threadIdx.y;
    tile[threadIdx.y][threadIdx.x] = in[y * G4 + x];
    __syncthreads();
    int ox = blockIdx.y * 32 + threadIdx.x;
    int oy = blockIdx.x * 32 + threadIdx.y;
    out[oy * HH + ox] = tile[threadIdx.x][threadIdx.y];
}

// ---------- multi-segment SGEMM (champion path, no flags) ----------
__global__ __launch_bounds__(256, 2)
void sgemm_ms(const float* __restrict__ A0, const float* __restrict__ A1,
              const float* __restrict__ B0, const float* __restrict__ B1,
              float* __restrict__ C, int M, int N, int nseg, int accum) {
    cudaTriggerProgrammaticLaunchCompletion();
    __shared__ __align__(16) float As[2][16][128];
    __shared__ __align__(16) float Bs[2][16][128];
    int tid = threadIdx.x;
    int m0 = blockIdx.y * 128, n0 = blockIdx.x * 128;
    int tr = tid >> 4, tc = tid & 15;
    int rowA = m0 + tr * 8, colB = n0 + tc * 8;
    int rA = tid >> 2, cA = (tid & 3) * 4;
    int rB = tid >> 5, cB = (tid & 31) * 4;

    unsigned long long acc[8][4];
#pragma unroll
    for (int i = 0; i < 8; i++)
#pragma unroll
        for (int p2 = 0; p2 < 4; p2++) acc[i][p2] = 0ull;

    int total = nseg * 16;
    float4 la0, la1, lb0, lb1;

#define LD_IT(IT)                                                              \
    {   int seg = (IT) >> 4, k0 = ((IT) & 15) << 4;                            \
        const float* Aseg = seg == 0 ? A0 : A1;                                \
        const float* Bseg = seg == 0 ? B0 : B1;                                \
        const float* Ap = Aseg + (size_t)(m0 + rA) * 256 + k0 + cA;            \
        la0 = *(const float4*)Ap;                                              \
        la1 = *(const float4*)(Ap + 64 * 256);                                 \
        const float* Bp = Bseg + (size_t)(k0 + rB) * N + n0 + cB;              \
        lb0 = *(const float4*)Bp;                                              \
        lb1 = *(const float4*)(Bp + 8 * N); }
#define ST_IT(P)                                                               \
    {   As[P][cA + 0][rA] = la0.x; As[P][cA + 1][rA] = la0.y;                  \
        As[P][cA + 2][rA] = la0.z; As[P][cA + 3][rA] = la0.w;                  \
        As[P][cA + 0][rA + 64] = la1.x; As[P][cA + 1][rA + 64] = la1.y;        \
        As[P][cA + 2][rA + 64] = la1.z; As[P][cA + 3][rA + 64] = la1.w;        \
        *(float4*)&Bs[P][rB][cB] = lb0;                                        \
        *(float4*)&Bs[P][rB + 8][cB] = lb1; }

    LD_IT(0); ST_IT(0);
    __syncthreads();
    int p = 0;
    for (int it = 0; it < total; ++it) {
        if (it + 1 < total) LD_IT(it + 1);
#pragma unroll
        for (int kk = 0; kk < 16; kk++) {
            float4 a0 = *(const float4*)&As[p][kk][tr * 8];
            float4 a1 = *(const float4*)&As[p][kk][tr * 8 + 4];
            ulonglong2 b0 = *(const ulonglong2*)&Bs[p][kk][tc * 8];
            ulonglong2 b1 = *(const ulonglong2*)&Bs[p][kk][tc * 8 + 4];
            float av[8] = {a0.x, a0.y, a0.z, a0.w, a1.x, a1.y, a1.z, a1.w};
#pragma unroll
            for (int i = 0; i < 8; i++) {
                unsigned long long s = splat2(av[i]);
                acc[i][0] = fma2(s, b0.x, acc[i][0]);
                acc[i][1] = fma2(s, b0.y, acc[i][1]);
                acc[i][2] = fma2(s, b1.x, acc[i][2]);
                acc[i][3] = fma2(s, b1.y, acc[i][3]);
            }
        }
        if (it + 1 < total) ST_IT(1 - p);
        __syncthreads();
        p ^= 1;
    }
#pragma unroll
    for (int i = 0; i < 8; i++) {
        float* cp = C + (size_t)(rowA + i) * N + colB;
#pragma unroll
        for (int p2 = 0; p2 < 4; p2++) {
            float2 v = unpk(acc[i][p2]);
            if (accum) { v.x += cp[2 * p2]; v.y += cp[2 * p2 + 1]; }
            cp[2 * p2] = v.x; cp[2 * p2 + 1] = v.y;
        }
    }
#undef LD_IT
#undef ST_IT
}

// ---------- persistent G producer: 128 CTAs, G = x@B0 + hn@B1, chunk flags ----------
// CTA L: b = L>>3, xt = L&7; loops tch 0..7. All 128 CTAs fit one wave ->
// PDL trigger at entry fires immediately, letting dec launch and chase flags.
__global__ __launch_bounds__(256, 2)
void sgemm_G_persist(const float* __restrict__ A0, const float* __restrict__ A1,
                     const float* __restrict__ B0, const float* __restrict__ B1,
                     float* __restrict__ C, int* flag) {
    cudaTriggerProgrammaticLaunchCompletion();
    __shared__ __align__(16) float As[2][16][128];
    __shared__ __align__(16) float Bs[2][16][128];
    const int N = G4;
    int tid = threadIdx.x;
    int L = blockIdx.x;
    int b = L >> 3, xt = L & 7;
    int n0 = xt * 128;
    int tr = tid >> 4, tc = tid & 15;
    int rA = tid >> 2, cA = (tid & 3) * 4;
    int rB = tid >> 5, cB = (tid & 31) * 4;

    for (int tch = 0; tch < 8; ++tch) {
        int m0 = (b * 8 + tch) * 128;
        int rowA = m0 + tr * 8, colB = n0 + tc * 8;

        unsigned long long acc[8][4];
#pragma unroll
        for (int i = 0; i < 8; i++)
#pragma unroll
            for (int p2 = 0; p2 < 4; p2++) acc[i][p2] = 0ull;

        float4 la0, la1, lb0, lb1;
#define LD_IT(IT)                                                              \
    {   int seg = (IT) >> 4, k0 = ((IT) & 15) << 4;                            \
        const float* Aseg = seg == 0 ? A0 : A1;                                \
        const float* Bseg = seg == 0 ? B0 : B1;                                \
        const float* Ap = Aseg + (size_t)(m0 + rA) * 256 + k0 + cA;            \
        la0 = *(const float4*)Ap;                                              \
        la1 = *(const float4*)(Ap + 64 * 256);                                 \
        const float* Bp = Bseg + (size_t)(k0 + rB) * N + n0 + cB;              \
        lb0 = *(const float4*)Bp;                                              \
        lb1 = *(const float4*)(Bp + 8 * N); }
#define ST_IT(P)                                                               \
    {   As[P][cA + 0][rA] = la0.x; As[P][cA + 1][rA] = la0.y;                  \
        As[P][cA + 2][rA] = la0.z; As[P][cA + 3][rA] = la0.w;                  \
        As[P][cA + 0][rA + 64] = la1.x; As[P][cA + 1][rA + 64] = la1.y;        \
        As[P][cA + 2][rA + 64] = la1.z; As[P][cA + 3][rA + 64] = la1.w;        \
        *(float4*)&Bs[P][rB][cB] = lb0;                                        \
        *(float4*)&Bs[P][rB + 8][cB] = lb1; }

        LD_IT(0); ST_IT(0);
        __syncthreads();
        int p = 0;
        for (int it = 0; it < 32; ++it) {   // 2 segments x 16
            if (it + 1 < 32) LD_IT(it + 1);
#pragma unroll
            for (int kk = 0; kk < 16; kk++) {
                float4 a0 = *(const float4*)&As[p][kk][tr * 8];
                float4 a1 = *(const float4*)&As[p][kk][tr * 8 + 4];
                ulonglong2 b0 = *(const ulonglong2*)&Bs[p][kk][tc * 8];
                ulonglong2 b1 = *(const ulonglong2*)&Bs[p][kk][tc * 8 + 4];
                float av[8] = {a0.x, a0.y, a0.z, a0.w, a1.x, a1.y, a1.z, a1.w};
#pragma unroll
                for (int i = 0; i < 8; i++) {
                    unsigned long long s = splat2(av[i]);
                    acc[i][0] = fma2(s, b0.x, acc[i][0]);
                    acc[i][1] = fma2(s, b0.y, acc[i][1]);
                    acc[i][2] = fma2(s, b1.x, acc[i][2]);
                    acc[i][3] = fma2(s, b1.y, acc[i][3]);
                }
            }
            if (it + 1 < 32) ST_IT(1 - p);
            __syncthreads();
            p ^= 1;
        }
#pragma unroll
        for (int i = 0; i < 8; i++) {
            float* cp = C + (size_t)(rowA + i) * N + colB;
#pragma unroll
            for (int p2 = 0; p2 < 4; p2++) {
                float2 v = unpk(acc[i][p2]);
                cp[2 * p2] = v.x; cp[2 * p2 + 1] = v.y;
            }
        }
        __threadfence();
        __syncthreads();
        if (tid == 0) atomicAdd(&flag[tch * 16 + b], 1);
        __syncthreads();
#undef LD_IT
#undef ST_IT
    }
}

// ======================================================================
// Weight-stationary cluster LSTMs — champion structure verbatim.
// ======================================================================

// ---------- encoder: 16 clusters (dir x batch-pair) = 128 CTAs ----------
__global__ __launch_bounds__(512, 1) __cluster_dims__(8, 1, 1)
void lstm_enc(const float* __restrict__ Af, const float* __restrict__ Ab,
              const float* __restrict__ WTf, const float* __restrict__ WTb,
              const float* __restrict__ bf, const float* __restrict__ bbp,
              float* __restrict__ hn, float* __restrict__ hb) {
    cudaTriggerProgrammaticLaunchCompletion();
    int r   = blockIdx.x & 7;
    int cid = blockIdx.x >> 3;
    int d   = cid >> 3;
    int pr  = cid & 7;
    int b0 = 2 * pr, b1 = 2 * pr + 1;
    const float* A    = d ? Ab  : Af;
    const float* WT   = d ? WTb : WTf;
    const float* bias = d ? bbp : bf;
    float* H          = d ? hb  : hn;

    __shared__ __align__(16) float hs[2][2][HH];
    __shared__ float zp[2][4][128];

    int tid = threadIdx.x;
    int q  = tid >> 7;               // UNIFORM PER WARP (broadcast LDS)
    int lr = tid & 127;
    int row = (lr >> 5) * 256 + r * 32 + (lr & 31);

    unsigned long long w2[32];
    {
        const ulonglong2* wp = (const ulonglong2*)(WT + (size_t)row * 256 + q * 64);
#pragma unroll
        for (int i = 0; i < 16; i++) { ulonglong2 v = wp[i]; w2[2*i] = v.x; w2[2*i+1] = v.y; }
    }

    bool upd = tid < 64;
    int ub = tid >> 5, uk = tid & 31;
    int bq = ub ? b1 : b0;
    float c = 0.f;
    float bias4[4];
    const float* Abase = A + ((size_t)(bq * SS)) * G4 + r * 32 + uk;
    float av_cur[4];
    if (upd) {
#pragma unroll
        for (int g = 0; g < 4; g++) bias4[g] = bias[g * 256 + r * 32 + uk];
        int t0 = d ? (SS - 1) : 0;
#pragma unroll
        for (int g = 0; g < 4; g++) av_cur[g] = __ldg(Abase + (size_t)t0 * G4 + g * 256);
    }
    hs[0][tid >> 8][tid & 255] = 0.f;
    __syncthreads();
    cluster_sync();

    int p = 0;
    for (int step = 0; step < SS; ++step) {
        int t = d ? (SS - 1 - step) : step;
        float av_nxt[4];
        if (upd && step + 1 < SS) {
            int t2 = d ? (SS - 2 - step) : (step + 1);
#pragma unroll
            for (int g = 0; g < 4; g++) av_nxt[g] = __ldg(Abase + (size_t)t2 * G4 + g * 256);
        }

        unsigned long long a0a = 0ull, a0b = 0ull, a1a = 0ull, a1b = 0ull;
        const ulonglong2* h0 = (const ulonglong2*)&hs[p][0][q * 64];
        const ulonglong2* h1 = (const ulonglong2*)&hs[p][1][q * 64];
#pragma unroll
        for (int i = 0; i < 16; i++) {
            ulonglong2 x0 = h0[i], x1 = h1[i];
            a0a = fma2(x0.x, w2[2*i], a0a); a0b = fma2(x0.y, w2[2*i+1], a0b);
            a1a = fma2(x1.x, w2[2*i], a1a); a1b = fma2(x1.y, w2[2*i+1], a1b);
        }
        float2 u0 = unpk(fma2(splat2(1.f), a0a, a0b));
        float2 u1 = unpk(fma2(splat2(1.f), a1a, a1b));
        zp[0][q][lr] = u0.x + u0.y;
        zp[1][q][lr] = u1.x + u1.y;
        __syncthreads();

        float hval = 0.f;
        if (upd) {
            float z[4];
#pragma unroll
            for (int g = 0; g < 4; g++) {
                int l = g * 32 + uk;
                z[g] = zp[ub][0][l] + zp[ub][1][l] + zp[ub][2][l] + zp[ub][3][l]
                     + av_cur[g] + bias4[g];
            }
            float iv = sigf(z[0]), fv = sigf(z[1]);
            float gv = tanhf(z[2]), ov = sigf(z[3]);
            c = fv * c + iv * gv;
            hval = ov * tanhf(c);
            int k = r * 32 + uk;
            unsigned int base = smem_u32(&hs[1 - p][ub][k]);
#pragma unroll
            for (int cta = 0; cta < 8; cta++) st_cluster_f32(base, cta, hval);
        }
        asm volatile("barrier.cluster.arrive.aligned;" ::: "memory");
        if (upd) {
            H[((size_t)(bq * SS + t)) * HH + (r * 32 + uk)] = hval;
#pragma unroll
            for (int g = 0; g < 4; g++) av_cur[g] = av_nxt[g];
        }
        asm volatile("barrier.cluster.wait.aligned;" ::: "memory");
        p ^= 1;
    }
}

// ---------- decoder: 8 clusters (2 batches each) = 64 CTAs ----------
__global__ __launch_bounds__(512, 1) __cluster_dims__(8, 1, 1)
void lstm_dec(const float* __restrict__ G, const float* __restrict__ WT,
              const float* __restrict__ bias, const float* __restrict__ hn,
              const float* __restrict__ P, const float* __restrict__ b3,
              const float* __restrict__ W4, const float* __restrict__ vt1,
              float* __restrict__ out, const int* __restrict__ flagG) {
    int r   = blockIdx.x & 7;
    int cid = blockIdx.x >> 3;
    int b0 = 2 * cid, b1 = 2 * cid + 1;

    __shared__ __align__(16) float hs[2][2][HH];
    __shared__ float zp[2][4][128];
    __shared__ __align__(16) float qp[2][WT_];
    __shared__ __align__(16) float qv[WT_];
    __shared__ __align__(16) float vs[WT_];
    __shared__ float rs[16];
    __shared__ int   ri[16];
    __shared__ int   bond_s[2];

    int tid = threadIdx.x;
    int q  = tid >> 7;
    int lr = tid & 127;
    int row = (lr >> 5) * 256 + r * 32 + (lr & 31);

    unsigned long long w2[32];
    {
        const ulonglong2* wp = (const ulonglong2*)(WT + (size_t)row * 256 + q * 64);
#pragma unroll
        for (int i = 0; i < 16; i++) { ulonglong2 v = wp[i]; w2[2*i] = v.x; w2[2*i+1] = v.y; }
    }

    bool upd = tid < 64;
    int ub = tid >> 5, uk = tid & 31;
    int bq = ub ? b1 : b0;
    float c = 0.f;
    float bias4[4];
    const float* Gbase = G + ((size_t)(bq * SS)) * G4 + r * 32 + uk;
    float av_cur[4] = {0.f, 0.f, 0.f, 0.f};
    if (upd) {
#pragma unroll
        for (int g = 0; g < 4; g++) bias4[g] = bias[g * 256 + r * 32 + uk];
        c = hn[((size_t)(bq * SS + SS - 1)) * HH + r * 32 + uk];
    }
    hs[0][tid >> 8][tid & 255] = 0.f;
    if (tid < 256) vs[tid] = vt1[tid];
    if (tid < 2)   bond_s[tid] = 0;
    if (r == 0) {
        for (int i = tid; i < SS; i += 512) {
            out[(size_t)i * BB + b0] = 0.f;
            out[(size_t)i * BB + b1] = 0.f;
        }
    }
    __syncthreads();
    cluster_sync();

    int p = 0;
    for (int t = 0; t < SS; ++t) {
        float av_nxt[4];
        if (upd && t + 1 < SS) {
            if ((t & 127) == 0) {    // wait for this G t-chunk (producer launched BEFORE us)
                const int* fp = flagG + ((t >> 7) << 4) + bq;
                while (ld_acq(fp) < 8) {}
            }
#pragma unroll
            for (int g = 0; g < 4; g++) av_nxt[g] = __ldg(Gbase + (size_t)t * G4 + g * 256);
        }

        unsigned long long a0a = 0ull, a0b = 0ull, a1a = 0ull, a1b = 0ull;
        const ulonglong2* h0 = (const ulonglong2*)&hs[p][0][q * 64];
        const ulonglong2* h1 = (const ulonglong2*)&hs[p][1][q * 64];
#pragma unroll
        for (int i = 0; i < 16; i++) {
            ulonglong2 x0 = h0[i], x1 = h1[i];
            a0a = fma2(x0.x, w2[2*i], a0a); a0b = fma2(x0.y, w2[2*i+1], a0b);
            a1a = fma2(x1.x, w2[2*i], a1a); a1b = fma2(x1.y, w2[2*i+1], a1b);
        }
        float2 u0 = unpk(fma2(splat2(1.f), a0a, a0b));
        float2 u1 = unpk(fma2(splat2(1.f), a1a, a1b));
        zp[0][q][lr] = u0.x + u0.y;
        zp[1][q][lr] = u1.x + u1.y;
        __syncthreads();

        if (upd) {
            float z[4];
#pragma unroll
            for (int g = 0; g < 4; g++) {
                int l = g * 32 + uk;
                z[g] = zp[ub][0][l] + zp[ub][1][l] + zp[ub][2][l] + zp[ub][3][l]
                     + av_cur[g] + bias4[g];
            }
            float iv = sigf(z[0]), fv = sigf(z[1]);
            float gv = tanhf(z[2]), ov = sigf(z[3]);
            c = fv * c + iv * gv;
            float h = ov * tanhf(c);
            int k = r * 32 + uk;
            unsigned int base = smem_u32(&hs[1 - p][ub][k]);
#pragma unroll
            for (int cta = 0; cta < 8; cta++) st_cluster_f32(base, cta, h);
        }
        asm volatile("barrier.cluster.arrive.aligned;" ::: "memory");
        if (upd) {
#pragma unroll
            for (int g = 0; g < 4; g++) av_cur[g] = av_nxt[g];
        }
        asm volatile("barrier.cluster.wait.aligned;" ::: "memory");
        p ^= 1;

        // ---- decision steps: replicated identically in all 8 CTAs ----
#pragma unroll 1
        for (int bat = 0; bat < 2; ++bat) {
            if (t != bond_s[bat]) continue;
            int b = bat ? b1 : b0;
            {
                int j = tid & 255, kh = tid >> 8;
                const float* w4p = W4 + (size_t)(kh * 128) * WT_ + j;
                const float* hh = &hs[p][bat][kh * 128];
                float acc = 0.f;
#pragma unroll 4
                for (int k = 0; k < 128; ++k) acc += hh[k] * w4p[(size_t)k * WT_];
                qp[kh][j] = acc;
            }
            __syncthreads();
            if (tid < 256)
                qv[tid] = qp[0][tid] + qp[1][tid] + b3[((size_t)(b * SS + t)) * WT_ + tid];
            __syncthreads();
            int wp = tid >> 5, lane = tid & 31;
            float best = -3.4e38f; int bi = 0x7fffffff;
            for (int pos = t + wp; pos < SS; pos += 16) {
                const float* Pr = P + ((size_t)(b * SS + pos)) * WT_;
                float4 p0 = *(const float4*)(Pr + lane * 4);
                float4 p1 = *(const float4*)(Pr + 128 + lane * 4);
                const float4 q0 = *(const float4*)(qv + lane * 4);
                const float4 q1 = *(const float4*)(qv + 128 + lane * 4);
                const float4 v0 = *(const float4*)(vs + lane * 4);
                const float4 v1 = *(const float4*)(vs + 128 + lane * 4);
                float s = v0.x * tanhf(p0.x + q0.x) + v0.y * tanhf(p0.y + q0.y)
                        + v0.z * tanhf(p0.z + q0.z) + v0.w * tanhf(p0.w + q0.w)
                        + v1.x * tanhf(p1.x + q1.x) + v1.y * tanhf(p1.y + q1.y)
                        + v1.z * tanhf(p1.z + q1.z) + v1.w * tanhf(p1.w + q1.w);
#pragma unroll
                for (int off = 16; off > 0; off >>= 1)
                    s += __shfl_down_sync(0xffffffffu, s, off);
                s = __shfl_sync(0xffffffffu, s, 0);
                if (s > best) { best = s; bi = pos; }
            }
            if (lane == 0) { rs[wp] = best; ri[wp] = bi; }
            __syncthreads();
            if (tid == 0) {
                float bb = rs[0]; int bx = ri[0];
#pragma unroll
                for (int w = 1; w < 16; w++)
                    if (rs[w] > bb || (rs[w] == bb && ri[w] < bx)) { bb = rs[w]; bx = ri[w]; }
                bond_s[bat] = bx;
                if (r == 0) out[(size_t)bx * BB + b] = 1.0f;
            }
            __syncthreads();
        }
    }
}

static void launch_gemm(const float* A0, const float* A1,
                        const float* B0, const float* B1,
                        float* C, int M, int N, int nseg, int accum, int pdl) {
    cudaLaunchConfig_t cfg = {};
    cfg.gridDim  = dim3(N / 128, M / 128, 1);
    cfg.blockDim = dim3(256, 1, 1);
    cfg.stream   = 0;
    cudaLaunchAttribute at[1];
    at[0].id = cudaLaunchAttributeProgrammaticStreamSerialization;
    at[0].val.programmaticStreamSerializationAllowed = 1;
    if (pdl) { cfg.attrs = at; cfg.numAttrs = 1; }
    cudaLaunchKernelEx(&cfg, sgemm_ms, A0, A1, B0, B1, C, M, N, nseg, accum);
}

extern "C" void kernel_launch(void* const* d_in, const int* in_sizes, int n_in,
                              void* d_out, int out_size) {
    const float* x        = (const float*)d_in[0];
    const float* eWih_f   = (const float*)d_in[1];
    const float* eWhh_f   = (const float*)d_in[2];
    const float* eb_f     = (const float*)d_in[3];
    const float* eWih_b   = (const float*)d_in[4];
    const float* eWhh_b   = (const float*)d_in[5];
    const float* eb_b     = (const float*)d_in[6];
    const float* dWih     = (const float*)d_in[7];
    const float* dWhh     = (const float*)d_in[8];
    const float* db       = (const float*)d_in[9];
    const float* W1       = (const float*)d_in[10];
    const float* W2       = (const float*)d_in[11];
    const float* W3       = (const float*)d_in[12];
    const float* W4       = (const float*)d_in[13];
    const float* vt1      = (const float*)d_in[14];
    float* out = (float*)d_out;

    float *Af, *Ab, *G, *hn, *hb, *P, *b3, *WTf, *WTb, *WTd;
    int *flagG;
    cudaGetSymbolAddress((void**)&Af,  g_Af);
    cudaGetSymbolAddress((void**)&Ab,  g_Ab);
    cudaGetSymbolAddress((void**)&G,   g_G);
    cudaGetSymbolAddress((void**)&hn,  g_hn);
    cudaGetSymbolAddress((void**)&hb,  g_hb);
    cudaGetSymbolAddress((void**)&P,   g_P);
    cudaGetSymbolAddress((void**)&b3,  g_b3);
    cudaGetSymbolAddress((void**)&WTf, g_WTf);
    cudaGetSymbolAddress((void**)&WTb, g_WTb);
    cudaGetSymbolAddress((void**)&WTd, g_WTd);
    cudaGetSymbolAddress((void**)&flagG, g_flagG);

    cudaMemsetAsync(flagG, 0, 128 * sizeof(int), 0);

    dim3 tb(32, 32), tg(G4 / 32, HH / 32, 3);
    transpose_w3<<<tg, tb>>>(eWhh_f, eWhh_b, dWhh, WTf, WTb, WTd);

    const int M = BB * SS;
    // encoder input projections (must complete before enc)
    launch_gemm(x, 0, eWih_f, 0, Af, M, G4, 1, 0, 0);
    launch_gemm(x, 0, eWih_b, 0, Ab, M, G4, 1, 0, 0);

    lstm_enc<<<128, 512>>>(Af, Ab, WTf, WTb, eb_f, eb_b, hn, hb);

    // x-only GEMMs hidden under enc (20 free SMs; 35.5 SM-ms fits the shadow)
    launch_gemm(x, 0, W2, 0, P,  M, WT_, 1, 0, 1);   // Px = x @ W2
    launch_gemm(x, 0, W3, 0, b3, M, WT_, 1, 0, 1);   // b3 = x @ W3

    // P accumulation (needs hn, hb, Px): full chip after enc
    launch_gemm(hn, hb, W1, W1 + HH * WT_, P, M, WT_, 2, 1, 0);

    // G PRODUCER FIRST (persistent 128 CTAs, one wave, triggers at entry,
    // publishes per-chunk flags). Fused: G = x@dWih_x + hn@dWih_h.
    sgemm_G_persist<<<128, 256>>>(x, hn, dWih, dWih + EE * G4, G, flagG);

    // dec SECOND with PSS: if PDL works it co-runs and chases the flags;
    // if PDL falls back to serialization, all flags are set before dec
    // starts and the spin passes instantly. Deadlock-free either way.
    {
        cudaLaunchConfig_t cfg = {};
        cfg.gridDim  = dim3(64, 1, 1);
        cfg.blockDim = dim3(512, 1, 1);
        cfg.stream   = 0;
        cudaLaunchAttribute at[1];
        at[0].id = cudaLaunchAttributeProgrammaticStreamSerialization;
        at[0].val.programmaticStreamSerializationAllowed = 1;
        cfg.attrs = at; cfg.numAttrs = 1;
        cudaLaunchKernelEx(&cfg, lstm_dec, (const float*)G, (const float*)WTd, db,
                           (const float*)hn, (const float*)P, (const float*)b3,
                           W4, vt1, out, (const int*)flagG);
    }
}

// round 16
// speedup vs baseline: 1.0769x; 1.0769x over previous
#include <cuda_runtime.h>
#include <math.h>

#define BB   16
#define SS   1024
#define EE   256
#define HH   256
#define G4   1024
#define WT_  256

// ---------- static scratch ----------
__device__ float g_Af[(size_t)BB * SS * G4];
__device__ float g_Ab[(size_t)BB * SS * G4];
__device__ float g_G [(size_t)BB * SS * G4];
__device__ float g_hn[(size_t)BB * SS * HH];
__device__ float g_hb[(size_t)BB * SS * HH];
__device__ float g_P [(size_t)BB * SS * WT_];
__device__ float g_b3[(size_t)BB * SS * WT_];
__device__ float g_WTf[G4 * HH];
__device__ float g_WTb[G4 * HH];
__device__ float g_WTd[G4 * HH];

// ---------- helpers ----------
__device__ __forceinline__ unsigned long long fma2(unsigned long long a,
                                                   unsigned long long b,
                                                   unsigned long long c) {
    unsigned long long d;
    asm("fma.rn.f32x2 %0, %1, %2, %3;" : "=l"(d) : "l"(a), "l"(b), "l"(c));
    return d;
}
__device__ __forceinline__ unsigned long long splat2(float a) {
    unsigned long long d; unsigned int u = __float_as_uint(a);
    asm("mov.b64 %0, {%1, %1};" : "=l"(d) : "r"(u));
    return d;
}
__device__ __forceinline__ float2 unpk(unsigned long long v) {
    float2 r;
    asm("mov.b64 {%0, %1}, %2;" : "=f"(r.x), "=f"(r.y) : "l"(v));
    return r;
}
__device__ __forceinline__ float sigf(float x) { return 1.0f / (1.0f + expf(-x)); }

__device__ __forceinline__ unsigned int smem_u32(const void* p) {
    unsigned int a;
    asm("{ .reg .u64 t; cvta.to.shared.u64 t, %1; cvt.u32.u64 %0, t; }" : "=r"(a) : "l"(p));
    return a;
}
__device__ __forceinline__ void st_cluster_f32(unsigned int addr, unsigned int rank, float v) {
    unsigned int ra;
    asm volatile("mapa.shared::cluster.u32 %0, %1, %2;" : "=r"(ra) : "r"(addr), "r"(rank));
    asm volatile("st.shared::cluster.f32 [%0], %1;" :: "r"(ra), "f"(v) : "memory");
}
__device__ __forceinline__ void cluster_sync() {
    asm volatile("barrier.cluster.arrive.aligned;" ::: "memory");
    asm volatile("barrier.cluster.wait.aligned;"   ::: "memory");
}

// ---------- fused transpose: 3x [256,1024] -> [1024,256] ----------
__global__ void transpose_w3(const float* __restrict__ i0, const float* __restrict__ i1,
                             const float* __restrict__ i2,
                             float* __restrict__ o0, float* __restrict__ o1,
                             float* __restrict__ o2) {
    const float* in  = blockIdx.z == 0 ? i0 : (blockIdx.z == 1 ? i1 : i2);
    float*       out = blockIdx.z == 0 ? o0 : (blockIdx.z == 1 ? o1 : o2);
    __shared__ float tile[32][33];
    int x = blockIdx.x * 32 + threadIdx.x;
    int y = blockIdx.y * 32 + threadIdx.y;
    tile[threadIdx.y][threadIdx.x] = in[y * G4 + x];
    __syncthreads();
    int ox = blockIdx.y * 32 + threadIdx.x;
    int oy = blockIdx.x * 32 + threadIdx.y;
    out[oy * HH + ox] = tile[threadIdx.x][threadIdx.y];
}

// ---------- shared GEMM inner machinery (identical math to champion) ----------
#define GEMM_BODY(A0_, A1_, B0_, B1_, C_, N_, NSEG_, ACCUM_, M0_, N0_)          \
    __shared__ __align__(16) float As[2][16][128];                              \
    __shared__ __align__(16) float Bs[2][16][128];                              \
    int tid = threadIdx.x;                                                      \
    int m0 = (M0_), n0 = (N0_);                                                 \
    int tr = tid >> 4, tc = tid & 15;                                           \
    int rowA = m0 + tr * 8, colB = n0 + tc * 8;                                 \
    int rA = tid >> 2, cA = (tid & 3) * 4;                                      \
    int rB = tid >> 5, cB = (tid & 31) * 4;                                     \
    unsigned long long acc[8][4];                                               \
    _Pragma("unroll")                                                           \
    for (int i = 0; i < 8; i++)                                                 \
        _Pragma("unroll")                                                       \
        for (int p2 = 0; p2 < 4; p2++) acc[i][p2] = 0ull;                       \
    int total = (NSEG_) * 16;                                                   \
    float4 la0, la1, lb0, lb1;                                                  \
    {   int k0 = 0;                                                             \
        const float* Ap = (A0_) + (size_t)(m0 + rA) * 256 + k0 + cA;            \
        la0 = *(const float4*)Ap; la1 = *(const float4*)(Ap + 64 * 256);        \
        const float* Bp = (B0_) + (size_t)(k0 + rB) * (N_) + n0 + cB;           \
        lb0 = *(const float4*)Bp; lb1 = *(const float4*)(Bp + 8 * (N_)); }      \
    As[0][cA + 0][rA] = la0.x; As[0][cA + 1][rA] = la0.y;                       \
    As[0][cA + 2][rA] = la0.z; As[0][cA + 3][rA] = la0.w;                       \
    As[0][cA + 0][rA + 64] = la1.x; As[0][cA + 1][rA + 64] = la1.y;             \
    As[0][cA + 2][rA + 64] = la1.z; As[0][cA + 3][rA + 64] = la1.w;             \
    *(float4*)&Bs[0][rB][cB] = lb0; *(float4*)&Bs[0][rB + 8][cB] = lb1;         \
    __syncthreads();                                                            \
    int p = 0;                                                                  \
    for (int it = 0; it < total; ++it) {                                        \
        if (it + 1 < total) {                                                   \
            int seg = (it + 1) >> 4, k0 = ((it + 1) & 15) << 4;                 \
            const float* Aseg = seg == 0 ? (A0_) : (A1_);                       \
            const float* Bseg = seg == 0 ? (B0_) : (B1_);                       \
            const float* Ap = Aseg + (size_t)(m0 + rA) * 256 + k0 + cA;         \
            la0 = *(const float4*)Ap; la1 = *(const float4*)(Ap + 64 * 256);    \
            const float* Bp = Bseg + (size_t)(k0 + rB) * (N_) + n0 + cB;        \
            lb0 = *(const float4*)Bp; lb1 = *(const float4*)(Bp + 8 * (N_));    \
        }                                                                       \
        _Pragma("unroll")                                                       \
        for (int kk = 0; kk < 16; kk++) {                                       \
            float4 a0 = *(const float4*)&As[p][kk][tr * 8];                     \
            float4 a1 = *(const float4*)&As[p][kk][tr * 8 + 4];                 \
            ulonglong2 b0 = *(const ulonglong2*)&Bs[p][kk][tc * 8];             \
            ulonglong2 b1 = *(const ulonglong2*)&Bs[p][kk][tc * 8 + 4];         \
            float av[8] = {a0.x, a0.y, a0.z, a0.w, a1.x, a1.y, a1.z, a1.w};     \
            _Pragma("unroll")                                                   \
            for (int i = 0; i < 8; i++) {                                       \
                unsigned long long s = splat2(av[i]);                           \
                acc[i][0] = fma2(s, b0.x, acc[i][0]);                           \
                acc[i][1] = fma2(s, b0.y, acc[i][1]);                           \
                acc[i][2] = fma2(s, b1.x, acc[i][2]);                           \
                acc[i][3] = fma2(s, b1.y, acc[i][3]);                           \
            }                                                                   \
        }                                                                       \
        if (it + 1 < total) {                                                   \
            int P2 = 1 - p;                                                     \
            As[P2][cA + 0][rA] = la0.x; As[P2][cA + 1][rA] = la0.y;             \
            As[P2][cA + 2][rA] = la0.z; As[P2][cA + 3][rA] = la0.w;             \
            As[P2][cA + 0][rA + 64] = la1.x; As[P2][cA + 1][rA + 64] = la1.y;   \
            As[P2][cA + 2][rA + 64] = la1.z; As[P2][cA + 3][rA + 64] = la1.w;   \
            *(float4*)&Bs[P2][rB][cB] = lb0;                                    \
            *(float4*)&Bs[P2][rB + 8][cB] = lb1;                                \
        }                                                                       \
        __syncthreads();                                                        \
        p ^= 1;                                                                 \
    }                                                                           \
    _Pragma("unroll")                                                           \
    for (int i = 0; i < 8; i++) {                                               \
        float* cp = (C_) + (size_t)(rowA + i) * (N_) + colB;                    \
        _Pragma("unroll")                                                       \
        for (int p2 = 0; p2 < 4; p2++) {                                        \
            float2 v = unpk(acc[i][p2]);                                        \
            if (ACCUM_) { v.x += cp[2 * p2]; v.y += cp[2 * p2 + 1]; }           \
            cp[2 * p2] = v.x; cp[2 * p2 + 1] = v.y;                             \
        }                                                                       \
    }

// ---------- single-output SGEMM (champion path; PDL trigger at entry) ----------
__global__ __launch_bounds__(256, 2)
void sgemm_ms(const float* __restrict__ A0, const float* __restrict__ A1,
              const float* __restrict__ B0, const float* __restrict__ B1,
              float* __restrict__ C, int M, int N, int nseg, int accum) {
    cudaTriggerProgrammaticLaunchCompletion();
    GEMM_BODY(A0, A1, B0, B1, C, N, nseg, accum,
              blockIdx.y * 128, blockIdx.x * 128)
}

// ---------- fused Af/Ab: z selects weight + output (same A = x) ----------
__global__ __launch_bounds__(256, 2)
void sgemm_af_ab(const float* __restrict__ x,
                 const float* __restrict__ Wf, const float* __restrict__ Wb,
                 float* __restrict__ Af, float* __restrict__ Ab) {
    cudaTriggerProgrammaticLaunchCompletion();
    const float* B = blockIdx.z ? Wb : Wf;
    float*       C = blockIdx.z ? Ab : Af;
    GEMM_BODY(x, x, B, B, C, G4, 1, 0,
              blockIdx.y * 128, blockIdx.x * 128)
}

// ---------- fused G_acc + P_acc: bx<8 -> G tile (1 seg), bx>=8 -> P tile (2 seg) ----------
__global__ __launch_bounds__(256, 2)
void sgemm_gp(const float* __restrict__ hn, const float* __restrict__ hb,
              const float* __restrict__ dWihh,
              const float* __restrict__ W1a, const float* __restrict__ W1b,
              float* __restrict__ G, float* __restrict__ P) {
    cudaTriggerProgrammaticLaunchCompletion();
    if (blockIdx.x < 8) {
        GEMM_BODY(hn, hn, dWihh, dWihh, G, G4, 1, 1,
                  blockIdx.y * 128, blockIdx.x * 128)
    } else {
        GEMM_BODY(hn, hb, W1a, W1b, P, WT_, 2, 1,
                  blockIdx.y * 128, (blockIdx.x - 8) * 128)
    }
}

// ======================================================================
// Weight-stationary cluster LSTMs — champion R11 verbatim.
// ======================================================================

// ---------- encoder: 16 clusters (dir x batch-pair) = 128 CTAs ----------
__global__ __launch_bounds__(512, 1) __cluster_dims__(8, 1, 1)
void lstm_enc(const float* __restrict__ Af, const float* __restrict__ Ab,
              const float* __restrict__ WTf, const float* __restrict__ WTb,
              const float* __restrict__ bf, const float* __restrict__ bbp,
              float* __restrict__ hn, float* __restrict__ hb) {
    cudaTriggerProgrammaticLaunchCompletion();
    int r   = blockIdx.x & 7;
    int cid = blockIdx.x >> 3;
    int d   = cid >> 3;
    int pr  = cid & 7;
    int b0 = 2 * pr, b1 = 2 * pr + 1;
    const float* A    = d ? Ab  : Af;
    const float* WT   = d ? WTb : WTf;
    const float* bias = d ? bbp : bf;
    float* H          = d ? hb  : hn;

    __shared__ __align__(16) float hs[2][2][HH];
    __shared__ float zp[2][4][128];

    int tid = threadIdx.x;
    int q  = tid >> 7;               // UNIFORM PER WARP (broadcast LDS)
    int lr = tid & 127;
    int row = (lr >> 5) * 256 + r * 32 + (lr & 31);

    unsigned long long w2[32];
    {
        const ulonglong2* wp = (const ulonglong2*)(WT + (size_t)row * 256 + q * 64);
#pragma unroll
        for (int i = 0; i < 16; i++) { ulonglong2 v = wp[i]; w2[2*i] = v.x; w2[2*i+1] = v.y; }
    }

    bool upd = tid < 64;
    int ub = tid >> 5, uk = tid & 31;
    int bq = ub ? b1 : b0;
    float c = 0.f;
    float bias4[4];
    const float* Abase = A + ((size_t)(bq * SS)) * G4 + r * 32 + uk;
    float av_cur[4];
    if (upd) {
#pragma unroll
        for (int g = 0; g < 4; g++) bias4[g] = bias[g * 256 + r * 32 + uk];
        int t0 = d ? (SS - 1) : 0;
#pragma unroll
        for (int g = 0; g < 4; g++) av_cur[g] = __ldg(Abase + (size_t)t0 * G4 + g * 256);
    }
    hs[0][tid >> 8][tid & 255] = 0.f;
    __syncthreads();
    cluster_sync();

    int p = 0;
    for (int step = 0; step < SS; ++step) {
        int t = d ? (SS - 1 - step) : step;
        float av_nxt[4];
        if (upd && step + 1 < SS) {
            int t2 = d ? (SS - 2 - step) : (step + 1);
#pragma unroll
            for (int g = 0; g < 4; g++) av_nxt[g] = __ldg(Abase + (size_t)t2 * G4 + g * 256);
        }

        unsigned long long a0a = 0ull, a0b = 0ull, a1a = 0ull, a1b = 0ull;
        const ulonglong2* h0 = (const ulonglong2*)&hs[p][0][q * 64];
        const ulonglong2* h1 = (const ulonglong2*)&hs[p][1][q * 64];
#pragma unroll
        for (int i = 0; i < 16; i++) {
            ulonglong2 x0 = h0[i], x1 = h1[i];
            a0a = fma2(x0.x, w2[2*i], a0a); a0b = fma2(x0.y, w2[2*i+1], a0b);
            a1a = fma2(x1.x, w2[2*i], a1a); a1b = fma2(x1.y, w2[2*i+1], a1b);
        }
        float2 u0 = unpk(fma2(splat2(1.f), a0a, a0b));
        float2 u1 = unpk(fma2(splat2(1.f), a1a, a1b));
        zp[0][q][lr] = u0.x + u0.y;
        zp[1][q][lr] = u1.x + u1.y;
        __syncthreads();

        float hval = 0.f;
        if (upd) {
            float z[4];
#pragma unroll
            for (int g = 0; g < 4; g++) {
                int l = g * 32 + uk;
                z[g] = zp[ub][0][l] + zp[ub][1][l] + zp[ub][2][l] + zp[ub][3][l]
                     + av_cur[g] + bias4[g];
            }
            float iv = sigf(z[0]), fv = sigf(z[1]);
            float gv = tanhf(z[2]), ov = sigf(z[3]);
            c = fv * c + iv * gv;
            hval = ov * tanhf(c);
            int k = r * 32 + uk;
            unsigned int base = smem_u32(&hs[1 - p][ub][k]);
#pragma unroll
            for (int cta = 0; cta < 8; cta++) st_cluster_f32(base, cta, hval);
        }
        asm volatile("barrier.cluster.arrive.aligned;" ::: "memory");
        if (upd) {
            H[((size_t)(bq * SS + t)) * HH + (r * 32 + uk)] = hval;
#pragma unroll
            for (int g = 0; g < 4; g++) av_cur[g] = av_nxt[g];
        }
        asm volatile("barrier.cluster.wait.aligned;" ::: "memory");
        p ^= 1;
    }
}

// ---------- decoder: 8 clusters (2 batches each) = 64 CTAs ----------
__global__ __launch_bounds__(512, 1) __cluster_dims__(8, 1, 1)
void lstm_dec(const float* __restrict__ G, const float* __restrict__ WT,
              const float* __restrict__ bias, const float* __restrict__ hn,
              const float* __restrict__ P, const float* __restrict__ b3,
              const float* __restrict__ W4, const float* __restrict__ vt1,
              float* __restrict__ out) {
    int r   = blockIdx.x & 7;
    int cid = blockIdx.x >> 3;
    int b0 = 2 * cid, b1 = 2 * cid + 1;

    __shared__ __align__(16) float hs[2][2][HH];
    __shared__ float zp[2][4][128];
    __shared__ __align__(16) float qp[2][WT_];
    __shared__ __align__(16) float qv[WT_];
    __shared__ __align__(16) float vs[WT_];
    __shared__ float rs[16];
    __shared__ int   ri[16];
    __shared__ int   bond_s[2];

    int tid = threadIdx.x;
    int q  = tid >> 7;
    int lr = tid & 127;
    int row = (lr >> 5) * 256 + r * 32 + (lr & 31);

    unsigned long long w2[32];
    {
        const ulonglong2* wp = (const ulonglong2*)(WT + (size_t)row * 256 + q * 64);
#pragma unroll
        for (int i = 0; i < 16; i++) { ulonglong2 v = wp[i]; w2[2*i] = v.x; w2[2*i+1] = v.y; }
    }

    bool upd = tid < 64;
    int ub = tid >> 5, uk = tid & 31;
    int bq = ub ? b1 : b0;
    float c = 0.f;
    float bias4[4];
    const float* Gbase = G + ((size_t)(bq * SS)) * G4 + r * 32 + uk;
    float av_cur[4] = {0.f, 0.f, 0.f, 0.f};
    if (upd) {
#pragma unroll
        for (int g = 0; g < 4; g++) bias4[g] = bias[g * 256 + r * 32 + uk];
        c = hn[((size_t)(bq * SS + SS - 1)) * HH + r * 32 + uk];
    }
    hs[0][tid >> 8][tid & 255] = 0.f;
    if (tid < 256) vs[tid] = vt1[tid];
    if (tid < 2)   bond_s[tid] = 0;
    if (r == 0) {
        for (int i = tid; i < SS; i += 512) {
            out[(size_t)i * BB + b0] = 0.f;
            out[(size_t)i * BB + b1] = 0.f;
        }
    }
    __syncthreads();
    cluster_sync();

    int p = 0;
    for (int t = 0; t < SS; ++t) {
        float av_nxt[4];
        if (upd && t + 1 < SS) {
#pragma unroll
            for (int g = 0; g < 4; g++) av_nxt[g] = __ldg(Gbase + (size_t)t * G4 + g * 256);
        }

        unsigned long long a0a = 0ull, a0b = 0ull, a1a = 0ull, a1b = 0ull;
        const ulonglong2* h0 = (const ulonglong2*)&hs[p][0][q * 64];
        const ulonglong2* h1 = (const ulonglong2*)&hs[p][1][q * 64];
#pragma unroll
        for (int i = 0; i < 16; i++) {
            ulonglong2 x0 = h0[i], x1 = h1[i];
            a0a = fma2(x0.x, w2[2*i], a0a); a0b = fma2(x0.y, w2[2*i+1], a0b);
            a1a = fma2(x1.x, w2[2*i], a1a); a1b = fma2(x1.y, w2[2*i+1], a1b);
        }
        float2 u0 = unpk(fma2(splat2(1.f), a0a, a0b));
        float2 u1 = unpk(fma2(splat2(1.f), a1a, a1b));
        zp[0][q][lr] = u0.x + u0.y;
        zp[1][q][lr] = u1.x + u1.y;
        __syncthreads();

        if (upd) {
            float z[4];
#pragma unroll
            for (int g = 0; g < 4; g++) {
                int l = g * 32 + uk;
                z[g] = zp[ub][0][l] + zp[ub][1][l] + zp[ub][2][l] + zp[ub][3][l]
                     + av_cur[g] + bias4[g];
            }
            float iv = sigf(z[0]), fv = sigf(z[1]);
            float gv = tanhf(z[2]), ov = sigf(z[3]);
            c = fv * c + iv * gv;
            float h = ov * tanhf(c);
            int k = r * 32 + uk;
            unsigned int base = smem_u32(&hs[1 - p][ub][k]);
#pragma unroll
            for (int cta = 0; cta < 8; cta++) st_cluster_f32(base, cta, h);
        }
        asm volatile("barrier.cluster.arrive.aligned;" ::: "memory");
        if (upd) {
#pragma unroll
            for (int g = 0; g < 4; g++) av_cur[g] = av_nxt[g];
        }
        asm volatile("barrier.cluster.wait.aligned;" ::: "memory");
        p ^= 1;

        // ---- decision steps: replicated identically in all 8 CTAs ----
#pragma unroll 1
        for (int bat = 0; bat < 2; ++bat) {
            if (t != bond_s[bat]) continue;
            int b = bat ? b1 : b0;
            {
                int j = tid & 255, kh = tid >> 8;
                const float* w4p = W4 + (size_t)(kh * 128) * WT_ + j;
                const float* hh = &hs[p][bat][kh * 128];
                float acc = 0.f;
#pragma unroll 4
                for (int k = 0; k < 128; ++k) acc += hh[k] * w4p[(size_t)k * WT_];
                qp[kh][j] = acc;
            }
            __syncthreads();
            if (tid < 256)
                qv[tid] = qp[0][tid] + qp[1][tid] + b3[((size_t)(b * SS + t)) * WT_ + tid];
            __syncthreads();
            int wp = tid >> 5, lane = tid & 31;
            float best = -3.4e38f; int bi = 0x7fffffff;
            for (int pos = t + wp; pos < SS; pos += 16) {
                const float* Pr = P + ((size_t)(b * SS + pos)) * WT_;
                float4 p0 = *(const float4*)(Pr + lane * 4);
                float4 p1 = *(const float4*)(Pr + 128 + lane * 4);
                const float4 q0 = *(const float4*)(qv + lane * 4);
                const float4 q1 = *(const float4*)(qv + 128 + lane * 4);
                const float4 v0 = *(const float4*)(vs + lane * 4);
                const float4 v1 = *(const float4*)(vs + 128 + lane * 4);
                float s = v0.x * tanhf(p0.x + q0.x) + v0.y * tanhf(p0.y + q0.y)
                        + v0.z * tanhf(p0.z + q0.z) + v0.w * tanhf(p0.w + q0.w)
                        + v1.x * tanhf(p1.x + q1.x) + v1.y * tanhf(p1.y + q1.y)
                        + v1.z * tanhf(p1.z + q1.z) + v1.w * tanhf(p1.w + q1.w);
#pragma unroll
                for (int off = 16; off > 0; off >>= 1)
                    s += __shfl_down_sync(0xffffffffu, s, off);
                s = __shfl_sync(0xffffffffu, s, 0);
                if (s > best) { best = s; bi = pos; }
            }
            if (lane == 0) { rs[wp] = best; ri[wp] = bi; }
            __syncthreads();
            if (tid == 0) {
                float bb = rs[0]; int bx = ri[0];
#pragma unroll
                for (int w = 1; w < 16; w++)
                    if (rs[w] > bb || (rs[w] == bb && ri[w] < bx)) { bb = rs[w]; bx = ri[w]; }
                bond_s[bat] = bx;
                if (r == 0) out[(size_t)bx * BB + b] = 1.0f;
            }
            __syncthreads();
        }
    }
}

static void launch_gemm(const float* A0, const float* A1,
                        const float* B0, const float* B1,
                        float* C, int M, int N, int nseg, int accum, int pdl) {
    cudaLaunchConfig_t cfg = {};
    cfg.gridDim  = dim3(N / 128, M / 128, 1);
    cfg.blockDim = dim3(256, 1, 1);
    cfg.stream   = 0;
    cudaLaunchAttribute at[1];
    at[0].id = cudaLaunchAttributeProgrammaticStreamSerialization;
    at[0].val.programmaticStreamSerializationAllowed = 1;
    if (pdl) { cfg.attrs = at; cfg.numAttrs = 1; }
    cudaLaunchKernelEx(&cfg, sgemm_ms, A0, A1, B0, B1, C, M, N, nseg, accum);
}

extern "C" void kernel_launch(void* const* d_in, const int* in_sizes, int n_in,
                              void* d_out, int out_size) {
    const float* x        = (const float*)d_in[0];
    const float* eWih_f   = (const float*)d_in[1];
    const float* eWhh_f   = (const float*)d_in[2];
    const float* eb_f     = (const float*)d_in[3];
    const float* eWih_b   = (const float*)d_in[4];
    const float* eWhh_b   = (const float*)d_in[5];
    const float* eb_b     = (const float*)d_in[6];
    const float* dWih     = (const float*)d_in[7];
    const float* dWhh     = (const float*)d_in[8];
    const float* db       = (const float*)d_in[9];
    const float* W1       = (const float*)d_in[10];
    const float* W2       = (const float*)d_in[11];
    const float* W3       = (const float*)d_in[12];
    const float* W4       = (const float*)d_in[13];
    const float* vt1      = (const float*)d_in[14];
    float* out = (float*)d_out;

    float *Af, *Ab, *G, *hn, *hb, *P, *b3, *WTf, *WTb, *WTd;
    cudaGetSymbolAddress((void**)&Af,  g_Af);
    cudaGetSymbolAddress((void**)&Ab,  g_Ab);
    cudaGetSymbolAddress((void**)&G,   g_G);
    cudaGetSymbolAddress((void**)&hn,  g_hn);
    cudaGetSymbolAddress((void**)&hb,  g_hb);
    cudaGetSymbolAddress((void**)&P,   g_P);
    cudaGetSymbolAddress((void**)&b3,  g_b3);
    cudaGetSymbolAddress((void**)&WTf, g_WTf);
    cudaGetSymbolAddress((void**)&WTb, g_WTb);
    cudaGetSymbolAddress((void**)&WTd, g_WTd);

    dim3 tb(32, 32), tg(G4 / 32, HH / 32, 3);
    transpose_w3<<<tg, tb>>>(eWhh_f, eWhh_b, dWhh, WTf, WTb, WTd);

    const int M = BB * SS;
    // fused encoder input projections (one launch: Af and Ab planes)
    sgemm_af_ab<<<dim3(G4 / 128, M / 128, 2), 256>>>(x, eWih_f, eWih_b, Af, Ab);

    lstm_enc<<<128, 512>>>(Af, Ab, WTf, WTb, eb_f, eb_b, hn, hb);

    // x-only GEMMs: PDL -> run on SMs left free by lstm_enc
    launch_gemm(x, 0, dWih, 0, G,  M, G4,  1, 0, 1);   // Gx = x @ dWih[:E]
    launch_gemm(x, 0, W2,   0, P,  M, WT_, 1, 0, 1);   // Px = x @ W2
    launch_gemm(x, 0, W3,   0, b3, M, WT_, 1, 0, 1);   // b3 = x @ W3

    // fused accumulations after enc: G += hn@dWih_h ; P += hn@W1a + hb@W1b
    sgemm_gp<<<dim3(10, M / 128, 1), 256>>>(hn, hb, dWih + EE * G4,
                                            W1, W1 + HH * WT_, G, P);

    lstm_dec<<<64, 512>>>(G, WTd, db, hn, P, b3, W4, vt1, out);
}

// round 17
// speedup vs baseline: 1.1616x; 1.0787x over previous
#include <cuda_runtime.h>
#include <math.h>

#define BB   16
#define SS   1024
#define EE   256
#define HH   256
#define G4   1024
#define WT_  256

// ---------- static scratch ----------
__device__ float g_Af[(size_t)BB * SS * G4];
__device__ float g_Ab[(size_t)BB * SS * G4];
__device__ float g_G [(size_t)BB * SS * G4];
__device__ float g_hn[(size_t)BB * SS * HH];
__device__ float g_hb[(size_t)BB * SS * HH];
__device__ float g_P [(size_t)BB * SS * WT_];
__device__ float g_b3[(size_t)BB * SS * WT_];
__device__ float g_WTf[G4 * HH];
__device__ float g_WTb[G4 * HH];
__device__ float g_WTd[G4 * HH];

// ---------- helpers ----------
__device__ __forceinline__ unsigned long long fma2(unsigned long long a,
                                                   unsigned long long b,
                                                   unsigned long long c) {
    unsigned long long d;
    asm("fma.rn.f32x2 %0, %1, %2, %3;" : "=l"(d) : "l"(a), "l"(b), "l"(c));
    return d;
}
__device__ __forceinline__ unsigned long long splat2(float a) {
    unsigned long long d; unsigned int u = __float_as_uint(a);
    asm("mov.b64 %0, {%1, %1};" : "=l"(d) : "r"(u));
    return d;
}
__device__ __forceinline__ float2 unpk(unsigned long long v) {
    float2 r;
    asm("mov.b64 {%0, %1}, %2;" : "=f"(r.x), "=f"(r.y) : "l"(v));
    return r;
}
// Fast transcendentals (MUFU-based). Sigmoid is NaN-free for all finite x;
// tanh input clamped to +-15 so __expf(2x) never overflows to inf (tanh(15)==1 in f32).
__device__ __forceinline__ float fsig(float x) {
    return __fdividef(1.0f, 1.0f + __expf(-x));
}
__device__ __forceinline__ float ftanh(float x) {
    x = fminf(fmaxf(x, -15.0f), 15.0f);
    float e = __expf(2.0f * x);
    return __fdividef(e - 1.0f, e + 1.0f);
}

__device__ __forceinline__ unsigned int smem_u32(const void* p) {
    unsigned int a;
    asm("{ .reg .u64 t; cvta.to.shared.u64 t, %1; cvt.u32.u64 %0, t; }" : "=r"(a) : "l"(p));
    return a;
}
__device__ __forceinline__ void st_cluster_f32(unsigned int addr, unsigned int rank, float v) {
    unsigned int ra;
    asm volatile("mapa.shared::cluster.u32 %0, %1, %2;" : "=r"(ra) : "r"(addr), "r"(rank));
    asm volatile("st.shared::cluster.f32 [%0], %1;" :: "r"(ra), "f"(v) : "memory");
}
__device__ __forceinline__ void cluster_sync() {
    asm volatile("barrier.cluster.arrive.aligned;" ::: "memory");
    asm volatile("barrier.cluster.wait.aligned;"   ::: "memory");
}

// ---------- fused transpose: 3x [256,1024] -> [1024,256] ----------
__global__ void transpose_w3(const float* __restrict__ i0, const float* __restrict__ i1,
                             const float* __restrict__ i2,
                             float* __restrict__ o0, float* __restrict__ o1,
                             float* __restrict__ o2) {
    const float* in  = blockIdx.z == 0 ? i0 : (blockIdx.z == 1 ? i1 : i2);
    float*       out = blockIdx.z == 0 ? o0 : (blockIdx.z == 1 ? o1 : o2);
    __shared__ float tile[32][33];
    int x = blockIdx.x * 32 + threadIdx.x;
    int y = blockIdx.y * 32 + threadIdx.y;
    tile[threadIdx.y][threadIdx.x] = in[y * G4 + x];
    __syncthreads();
    int ox = blockIdx.y * 32 + threadIdx.x;
    int oy = blockIdx.x * 32 + threadIdx.y;
    out[oy * HH + ox] = tile[threadIdx.x][threadIdx.y];
}

// ---------- shared GEMM inner machinery (identical math to champion) ----------
#define GEMM_BODY(A0_, A1_, B0_, B1_, C_, N_, NSEG_, ACCUM_, M0_, N0_)          \
    __shared__ __align__(16) float As[2][16][128];                              \
    __shared__ __align__(16) float Bs[2][16][128];                              \
    int tid = threadIdx.x;                                                      \
    int m0 = (M0_), n0 = (N0_);                                                 \
    int tr = tid >> 4, tc = tid & 15;                                           \
    int rowA = m0 + tr * 8, colB = n0 + tc * 8;                                 \
    int rA = tid >> 2, cA = (tid & 3) * 4;                                      \
    int rB = tid >> 5, cB = (tid & 31) * 4;                                     \
    unsigned long long acc[8][4];                                               \
    _Pragma("unroll")                                                           \
    for (int i = 0; i < 8; i++)                                                 \
        _Pragma("unroll")                                                       \
        for (int p2 = 0; p2 < 4; p2++) acc[i][p2] = 0ull;                       \
    int total = (NSEG_) * 16;                                                   \
    float4 la0, la1, lb0, lb1;                                                  \
    {   int k0 = 0;                                                             \
        const float* Ap = (A0_) + (size_t)(m0 + rA) * 256 + k0 + cA;            \
        la0 = *(const float4*)Ap; la1 = *(const float4*)(Ap + 64 * 256);        \
        const float* Bp = (B0_) + (size_t)(k0 + rB) * (N_) + n0 + cB;           \
        lb0 = *(const float4*)Bp; lb1 = *(const float4*)(Bp + 8 * (N_)); }      \
    As[0][cA + 0][rA] = la0.x; As[0][cA + 1][rA] = la0.y;                       \
    As[0][cA + 2][rA] = la0.z; As[0][cA + 3][rA] = la0.w;                       \
    As[0][cA + 0][rA + 64] = la1.x; As[0][cA + 1][rA + 64] = la1.y;             \
    As[0][cA + 2][rA + 64] = la1.z; As[0][cA + 3][rA + 64] = la1.w;             \
    *(float4*)&Bs[0][rB][cB] = lb0; *(float4*)&Bs[0][rB + 8][cB] = lb1;         \
    __syncthreads();                                                            \
    int p = 0;                                                                  \
    for (int it = 0; it < total; ++it) {                                        \
        if (it + 1 < total) {                                                   \
            int seg = (it + 1) >> 4, k0 = ((it + 1) & 15) << 4;                 \
            const float* Aseg = seg == 0 ? (A0_) : (A1_);                       \
            const float* Bseg = seg == 0 ? (B0_) : (B1_);                       \
            const float* Ap = Aseg + (size_t)(m0 + rA) * 256 + k0 + cA;         \
            la0 = *(const float4*)Ap; la1 = *(const float4*)(Ap + 64 * 256);    \
            const float* Bp = Bseg + (size_t)(k0 + rB) * (N_) + n0 + cB;        \
            lb0 = *(const float4*)Bp; lb1 = *(const float4*)(Bp + 8 * (N_));    \
        }                                                                       \
        _Pragma("unroll")                                                       \
        for (int kk = 0; kk < 16; kk++) {                                       \
            float4 a0 = *(const float4*)&As[p][kk][tr * 8];                     \
            float4 a1 = *(const float4*)&As[p][kk][tr * 8 + 4];                 \
            ulonglong2 b0 = *(const ulonglong2*)&Bs[p][kk][tc * 8];             \
            ulonglong2 b1 = *(const ulonglong2*)&Bs[p][kk][tc * 8 + 4];         \
            float av[8] = {a0.x, a0.y, a0.z, a0.w, a1.x, a1.y, a1.z, a1.w};     \
            _Pragma("unroll")                                                   \
            for (int i = 0; i < 8; i++) {                                       \
                unsigned long long s = splat2(av[i]);                           \
                acc[i][0] = fma2(s, b0.x, acc[i][0]);                           \
                acc[i][1] = fma2(s, b0.y, acc[i][1]);                           \
                acc[i][2] = fma2(s, b1.x, acc[i][2]);                           \
                acc[i][3] = fma2(s, b1.y, acc[i][3]);                           \
            }                                                                   \
        }                                                                       \
        if (it + 1 < total) {                                                   \
            int P2 = 1 - p;                                                     \
            As[P2][cA + 0][rA] = la0.x; As[P2][cA + 1][rA] = la0.y;             \
            As[P2][cA + 2][rA] = la0.z; As[P2][cA + 3][rA] = la0.w;             \
            As[P2][cA + 0][rA + 64] = la1.x; As[P2][cA + 1][rA + 64] = la1.y;   \
            As[P2][cA + 2][rA + 64] = la1.z; As[P2][cA + 3][rA + 64] = la1.w;   \
            *(float4*)&Bs[P2][rB][cB] = lb0;                                    \
            *(float4*)&Bs[P2][rB + 8][cB] = lb1;                                \
        }                                                                       \
        __syncthreads();                                                        \
        p ^= 1;                                                                 \
    }                                                                           \
    _Pragma("unroll")                                                           \
    for (int i = 0; i < 8; i++) {                                               \
        float* cp = (C_) + (size_t)(rowA + i) * (N_) + colB;                    \
        _Pragma("unroll")                                                       \
        for (int p2 = 0; p2 < 4; p2++) {                                        \
            float2 v = unpk(acc[i][p2]);                                        \
            if (ACCUM_) { v.x += cp[2 * p2]; v.y += cp[2 * p2 + 1]; }           \
            cp[2 * p2] = v.x; cp[2 * p2 + 1] = v.y;                             \
        }                                                                       \
    }

// ---------- single-output SGEMM ----------
__global__ __launch_bounds__(256, 2)
void sgemm_ms(const float* __restrict__ A0, const float* __restrict__ A1,
              const float* __restrict__ B0, const float* __restrict__ B1,
              float* __restrict__ C, int M, int N, int nseg, int accum) {
    cudaTriggerProgrammaticLaunchCompletion();
    GEMM_BODY(A0, A1, B0, B1, C, N, nseg, accum,
              blockIdx.y * 128, blockIdx.x * 128)
}

// ---------- fused Af/Ab ----------
__global__ __launch_bounds__(256, 2)
void sgemm_af_ab(const float* __restrict__ x,
                 const float* __restrict__ Wf, const float* __restrict__ Wb,
                 float* __restrict__ Af, float* __restrict__ Ab) {
    cudaTriggerProgrammaticLaunchCompletion();
    const float* B = blockIdx.z ? Wb : Wf;
    float*       C = blockIdx.z ? Ab : Af;
    GEMM_BODY(x, x, B, B, C, G4, 1, 0,
              blockIdx.y * 128, blockIdx.x * 128)
}

// ---------- fused G_acc + P_acc ----------
__global__ __launch_bounds__(256, 2)
void sgemm_gp(const float* __restrict__ hn, const float* __restrict__ hb,
              const float* __restrict__ dWihh,
              const float* __restrict__ W1a, const float* __restrict__ W1b,
              float* __restrict__ G, float* __restrict__ P) {
    cudaTriggerProgrammaticLaunchCompletion();
    if (blockIdx.x < 8) {
        GEMM_BODY(hn, hn, dWihh, dWihh, G, G4, 1, 1,
                  blockIdx.y * 128, blockIdx.x * 128)
    } else {
        GEMM_BODY(hn, hb, W1a, W1b, P, WT_, 2, 1,
                  blockIdx.y * 128, (blockIdx.x - 8) * 128)
    }
}

// ======================================================================
// Weight-stationary cluster LSTMs — champion structure; fast gates.
// ======================================================================

// ---------- encoder: 16 clusters (dir x batch-pair) = 128 CTAs ----------
__global__ __launch_bounds__(512, 1) __cluster_dims__(8, 1, 1)
void lstm_enc(const float* __restrict__ Af, const float* __restrict__ Ab,
              const float* __restrict__ WTf, const float* __restrict__ WTb,
              const float* __restrict__ bf, const float* __restrict__ bbp,
              float* __restrict__ hn, float* __restrict__ hb) {
    cudaTriggerProgrammaticLaunchCompletion();
    int r   = blockIdx.x & 7;
    int cid = blockIdx.x >> 3;
    int d   = cid >> 3;
    int pr  = cid & 7;
    int b0 = 2 * pr, b1 = 2 * pr + 1;
    const float* A    = d ? Ab  : Af;
    const float* WT   = d ? WTb : WTf;
    const float* bias = d ? bbp : bf;
    float* H          = d ? hb  : hn;

    __shared__ __align__(16) float hs[2][2][HH];
    __shared__ float zp[2][4][128];

    int tid = threadIdx.x;
    int q  = tid >> 7;               // UNIFORM PER WARP (broadcast LDS)
    int lr = tid & 127;
    int row = (lr >> 5) * 256 + r * 32 + (lr & 31);

    unsigned long long w2[32];
    {
        const ulonglong2* wp = (const ulonglong2*)(WT + (size_t)row * 256 + q * 64);
#pragma unroll
        for (int i = 0; i < 16; i++) { ulonglong2 v = wp[i]; w2[2*i] = v.x; w2[2*i+1] = v.y; }
    }

    bool upd = tid < 64;
    int ub = tid >> 5, uk = tid & 31;
    int bq = ub ? b1 : b0;
    float c = 0.f;
    float bias4[4];
    const float* Abase = A + ((size_t)(bq * SS)) * G4 + r * 32 + uk;
    float av_cur[4];
    if (upd) {
#pragma unroll
        for (int g = 0; g < 4; g++) bias4[g] = bias[g * 256 + r * 32 + uk];
        int t0 = d ? (SS - 1) : 0;
#pragma unroll
        for (int g = 0; g < 4; g++) av_cur[g] = __ldg(Abase + (size_t)t0 * G4 + g * 256);
    }
    hs[0][tid >> 8][tid & 255] = 0.f;
    __syncthreads();
    cluster_sync();

    int p = 0;
    for (int step = 0; step < SS; ++step) {
        int t = d ? (SS - 1 - step) : step;
        float av_nxt[4];
        if (upd && step + 1 < SS) {
            int t2 = d ? (SS - 2 - step) : (step + 1);
#pragma unroll
            for (int g = 0; g < 4; g++) av_nxt[g] = __ldg(Abase + (size_t)t2 * G4 + g * 256);
        }

        unsigned long long a0a = 0ull, a0b = 0ull, a1a = 0ull, a1b = 0ull;
        const ulonglong2* h0 = (const ulonglong2*)&hs[p][0][q * 64];
        const ulonglong2* h1 = (const ulonglong2*)&hs[p][1][q * 64];
#pragma unroll
        for (int i = 0; i < 16; i++) {
            ulonglong2 x0 = h0[i], x1 = h1[i];
            a0a = fma2(x0.x, w2[2*i], a0a); a0b = fma2(x0.y, w2[2*i+1], a0b);
            a1a = fma2(x1.x, w2[2*i], a1a); a1b = fma2(x1.y, w2[2*i+1], a1b);
        }
        float2 u0 = unpk(fma2(splat2(1.f), a0a, a0b));
        float2 u1 = unpk(fma2(splat2(1.f), a1a, a1b));
        zp[0][q][lr] = u0.x + u0.y;
        zp[1][q][lr] = u1.x + u1.y;
        __syncthreads();

        float hval = 0.f;
        if (upd) {
            float z[4];
#pragma unroll
            for (int g = 0; g < 4; g++) {
                int l = g * 32 + uk;
                z[g] = zp[ub][0][l] + zp[ub][1][l] + zp[ub][2][l] + zp[ub][3][l]
                     + av_cur[g] + bias4[g];
            }
            float iv = fsig(z[0]), fv = fsig(z[1]);
            float gv = ftanh(z[2]), ov = fsig(z[3]);
            c = fv * c + iv * gv;
            hval = ov * ftanh(c);
            int k = r * 32 + uk;
            unsigned int base = smem_u32(&hs[1 - p][ub][k]);
#pragma unroll
            for (int cta = 0; cta < 8; cta++) st_cluster_f32(base, cta, hval);
        }
        asm volatile("barrier.cluster.arrive.aligned;" ::: "memory");
        if (upd) {
            H[((size_t)(bq * SS + t)) * HH + (r * 32 + uk)] = hval;
#pragma unroll
            for (int g = 0; g < 4; g++) av_cur[g] = av_nxt[g];
        }
        asm volatile("barrier.cluster.wait.aligned;" ::: "memory");
        p ^= 1;
    }
}

// ---------- decoder: 8 clusters (2 batches each) = 64 CTAs ----------
__global__ __launch_bounds__(512, 1) __cluster_dims__(8, 1, 1)
void lstm_dec(const float* __restrict__ G, const float* __restrict__ WT,
              const float* __restrict__ bias, const float* __restrict__ hn,
              const float* __restrict__ P, const float* __restrict__ b3,
              const float* __restrict__ W4, const float* __restrict__ vt1,
              float* __restrict__ out) {
    int r   = blockIdx.x & 7;
    int cid = blockIdx.x >> 3;
    int b0 = 2 * cid, b1 = 2 * cid + 1;

    __shared__ __align__(16) float hs[2][2][HH];
    __shared__ float zp[2][4][128];
    __shared__ __align__(16) float qp[2][WT_];
    __shared__ __align__(16) float qv[WT_];
    __shared__ __align__(16) float vs[WT_];
    __shared__ float rs[16];
    __shared__ int   ri[16];
    __shared__ int   bond_s[2];

    int tid = threadIdx.x;
    int q  = tid >> 7;
    int lr = tid & 127;
    int row = (lr >> 5) * 256 + r * 32 + (lr & 31);

    unsigned long long w2[32];
    {
        const ulonglong2* wp = (const ulonglong2*)(WT + (size_t)row * 256 + q * 64);
#pragma unroll
        for (int i = 0; i < 16; i++) { ulonglong2 v = wp[i]; w2[2*i] = v.x; w2[2*i+1] = v.y; }
    }

    bool upd = tid < 64;
    int ub = tid >> 5, uk = tid & 31;
    int bq = ub ? b1 : b0;
    float c = 0.f;
    float bias4[4];
    const float* Gbase = G + ((size_t)(bq * SS)) * G4 + r * 32 + uk;
    float av_cur[4] = {0.f, 0.f, 0.f, 0.f};
    if (upd) {
#pragma unroll
        for (int g = 0; g < 4; g++) bias4[g] = bias[g * 256 + r * 32 + uk];
        c = hn[((size_t)(bq * SS + SS - 1)) * HH + r * 32 + uk];
    }
    hs[0][tid >> 8][tid & 255] = 0.f;
    if (tid < 256) vs[tid] = vt1[tid];
    if (tid < 2)   bond_s[tid] = 0;
    if (r == 0) {
        for (int i = tid; i < SS; i += 512) {
            out[(size_t)i * BB + b0] = 0.f;
            out[(size_t)i * BB + b1] = 0.f;
        }
    }
    __syncthreads();
    cluster_sync();

    int p = 0;
    for (int t = 0; t < SS; ++t) {
        float av_nxt[4];
        if (upd && t + 1 < SS) {
#pragma unroll
            for (int g = 0; g < 4; g++) av_nxt[g] = __ldg(Gbase + (size_t)t * G4 + g * 256);
        }

        unsigned long long a0a = 0ull, a0b = 0ull, a1a = 0ull, a1b = 0ull;
        const ulonglong2* h0 = (const ulonglong2*)&hs[p][0][q * 64];
        const ulonglong2* h1 = (const ulonglong2*)&hs[p][1][q * 64];
#pragma unroll
        for (int i = 0; i < 16; i++) {
            ulonglong2 x0 = h0[i], x1 = h1[i];
            a0a = fma2(x0.x, w2[2*i], a0a); a0b = fma2(x0.y, w2[2*i+1], a0b);
            a1a = fma2(x1.x, w2[2*i], a1a); a1b = fma2(x1.y, w2[2*i+1], a1b);
        }
        float2 u0 = unpk(fma2(splat2(1.f), a0a, a0b));
        float2 u1 = unpk(fma2(splat2(1.f), a1a, a1b));
        zp[0][q][lr] = u0.x + u0.y;
        zp[1][q][lr] = u1.x + u1.y;
        __syncthreads();

        if (upd) {
            float z[4];
#pragma unroll
            for (int g = 0; g < 4; g++) {
                int l = g * 32 + uk;
                z[g] = zp[ub][0][l] + zp[ub][1][l] + zp[ub][2][l] + zp[ub][3][l]
                     + av_cur[g] + bias4[g];
            }
            float iv = fsig(z[0]), fv = fsig(z[1]);
            float gv = ftanh(z[2]), ov = fsig(z[3]);
            c = fv * c + iv * gv;
            float h = ov * ftanh(c);
            int k = r * 32 + uk;
            unsigned int base = smem_u32(&hs[1 - p][ub][k]);
#pragma unroll
            for (int cta = 0; cta < 8; cta++) st_cluster_f32(base, cta, h);
        }
        asm volatile("barrier.cluster.arrive.aligned;" ::: "memory");
        if (upd) {
#pragma unroll
            for (int g = 0; g < 4; g++) av_cur[g] = av_nxt[g];
        }
        asm volatile("barrier.cluster.wait.aligned;" ::: "memory");
        p ^= 1;

        // ---- decision steps: replicated identically in all 8 CTAs ----
#pragma unroll 1
        for (int bat = 0; bat < 2; ++bat) {
            if (t != bond_s[bat]) continue;
            int b = bat ? b1 : b0;
            {
                int j = tid & 255, kh = tid >> 8;
                const float* w4p = W4 + (size_t)(kh * 128) * WT_ + j;
                const float* hh = &hs[p][bat][kh * 128];
                float acc = 0.f;
#pragma unroll 4
                for (int k = 0; k < 128; ++k) acc += hh[k] * w4p[(size_t)k * WT_];
                qp[kh][j] = acc;
            }
            __syncthreads();
            if (tid < 256)
                qv[tid] = qp[0][tid] + qp[1][tid] + b3[((size_t)(b * SS + t)) * WT_ + tid];
            __syncthreads();
            int wp = tid >> 5, lane = tid & 31;
            float best = -3.4e38f; int bi = 0x7fffffff;
            for (int pos = t + wp; pos < SS; pos += 16) {
                const float* Pr = P + ((size_t)(b * SS + pos)) * WT_;
                float4 p0 = *(const float4*)(Pr + lane * 4);
                float4 p1 = *(const float4*)(Pr + 128 + lane * 4);
                const float4 q0 = *(const float4*)(qv + lane * 4);
                const float4 q1 = *(const float4*)(qv + 128 + lane * 4);
                const float4 v0 = *(const float4*)(vs + lane * 4);
                const float4 v1 = *(const float4*)(vs + 128 + lane * 4);
                float s = v0.x * ftanh(p0.x + q0.x) + v0.y * ftanh(p0.y + q0.y)
                        + v0.z * ftanh(p0.z + q0.z) + v0.w * ftanh(p0.w + q0.w)
                        + v1.x * ftanh(p1.x + q1.x) + v1.y * ftanh(p1.y + q1.y)
                        + v1.z * ftanh(p1.z + q1.z) + v1.w * ftanh(p1.w + q1.w);
#pragma unroll
                for (int off = 16; off > 0; off >>= 1)
                    s += __shfl_down_sync(0xffffffffu, s, off);
                s = __shfl_sync(0xffffffffu, s, 0);
                if (s > best) { best = s; bi = pos; }
            }
            if (lane == 0) { rs[wp] = best; ri[wp] = bi; }
            __syncthreads();
            if (tid == 0) {
                float bb = rs[0]; int bx = ri[0];
#pragma unroll
                for (int w = 1; w < 16; w++)
                    if (rs[w] > bb || (rs[w] == bb && ri[w] < bx)) { bb = rs[w]; bx = ri[w]; }
                bond_s[bat] = bx;
                if (r == 0) out[(size_t)bx * BB + b] = 1.0f;
            }
            __syncthreads();
        }
    }
}

static void launch_gemm(const float* A0, const float* A1,
                        const float* B0, const float* B1,
                        float* C, int M, int N, int nseg, int accum, int pdl) {
    cudaLaunchConfig_t cfg = {};
    cfg.gridDim  = dim3(N / 128, M / 128, 1);
    cfg.blockDim = dim3(256, 1, 1);
    cfg.stream   = 0;
    cudaLaunchAttribute at[1];
    at[0].id = cudaLaunchAttributeProgrammaticStreamSerialization;
    at[0].val.programmaticStreamSerializationAllowed = 1;
    if (pdl) { cfg.attrs = at; cfg.numAttrs = 1; }
    cudaLaunchKernelEx(&cfg, sgemm_ms, A0, A1, B0, B1, C, M, N, nseg, accum);
}

extern "C" void kernel_launch(void* const* d_in, const int* in_sizes, int n_in,
                              void* d_out, int out_size) {
    const float* x        = (const float*)d_in[0];
    const float* eWih_f   = (const float*)d_in[1];
    const float* eWhh_f   = (const float*)d_in[2];
    const float* eb_f     = (const float*)d_in[3];
    const float* eWih_b   = (const float*)d_in[4];
    const float* eWhh_b   = (const float*)d_in[5];
    const float* eb_b     = (const float*)d_in[6];
    const float* dWih     = (const float*)d_in[7];
    const float* dWhh     = (const float*)d_in[8];
    const float* db       = (const float*)d_in[9];
    const float* W1       = (const float*)d_in[10];
    const float* W2       = (const float*)d_in[11];
    const float* W3       = (const float*)d_in[12];
    const float* W4       = (const float*)d_in[13];
    const float* vt1      = (const float*)d_in[14];
    float* out = (float*)d_out;

    float *Af, *Ab, *G, *hn, *hb, *P, *b3, *WTf, *WTb, *WTd;
    cudaGetSymbolAddress((void**)&Af,  g_Af);
    cudaGetSymbolAddress((void**)&Ab,  g_Ab);
    cudaGetSymbolAddress((void**)&G,   g_G);
    cudaGetSymbolAddress((void**)&hn,  g_hn);
    cudaGetSymbolAddress((void**)&hb,  g_hb);
    cudaGetSymbolAddress((void**)&P,   g_P);
    cudaGetSymbolAddress((void**)&b3,  g_b3);
    cudaGetSymbolAddress((void**)&WTf, g_WTf);
    cudaGetSymbolAddress((void**)&WTb, g_WTb);
    cudaGetSymbolAddress((void**)&WTd, g_WTd);

    dim3 tb(32, 32), tg(G4 / 32, HH / 32, 3);
    transpose_w3<<<tg, tb>>>(eWhh_f, eWhh_b, dWhh, WTf, WTb, WTd);

    const int M = BB * SS;
    // fused encoder input projections (one launch: Af and Ab planes)
    sgemm_af_ab<<<dim3(G4 / 128, M / 128, 2), 256>>>(x, eWih_f, eWih_b, Af, Ab);

    lstm_enc<<<128, 512>>>(Af, Ab, WTf, WTb, eb_f, eb_b, hn, hb);

    // x-only GEMMs: PDL -> run on SMs left free by lstm_enc
    launch_gemm(x, 0, dWih, 0, G,  M, G4,  1, 0, 1);   // Gx = x @ dWih[:E]
    launch_gemm(x, 0, W2,   0, P,  M, WT_, 1, 0, 1);   // Px = x @ W2
    launch_gemm(x, 0, W3,   0, b3, M, WT_, 1, 0, 1);   // b3 = x @ W3

    // fused accumulations after enc: G += hn@dWih_h ; P += hn@W1a + hb@W1b
    sgemm_gp<<<dim3(10, M / 128, 1), 256>>>(hn, hb, dWih + EE * G4,
                                            W1, W1 + HH * WT_, G, P);

    lstm_dec<<<64, 512>>>(G, WTd, db, hn, P, b3, W4, vt1, out);
}